// round 16
// baseline (speedup 1.0000x reference)
#include <cuda_runtime.h>
#include <cuda_fp16.h>
#include <cstdint>

#define N_EL     19
#define GPC      4                    // graphs per tile
#define ROWS     76                   // valid rows per tile
#define MPAD     80                   // 5 m16 tiles
#define N_GRAPHS 1800
#define C        128
#define NTILES   (N_GRAPHS / GPC)     // 450
#define TILES2   154                  // CTAs 0..153 take 2 tiles; rest 1
#define GRID     296                  // 154*2 + 142*1 = 450
#define NTHR     256

// pre-converted B image: [Wrel;Wroot] fp16, swizzled smem layout, 64 KB
__device__ __align__(16) char g_Bh[65536];

// smem map (bytes from dynamic base)
#define BOFF   0                      // B fp16: 8 k16-blocks x 256 rows x 32B
#define BBLK   8192
#define QOFF   0                      // Q fp32 overlays B after MMA1: 76 x 528B
#define QSTR   528
#define X0OFF  65536                  // X fp16: 8 blocks x 80 rows x 32B (+pad)
#define X1OFF  86144
#define XBLK   2576                   // 2560 + 16 pad -> conflict-free STS
#define PSTR   264                    // P fp16 row stride in dead X buffer
#define ASOFF  106752                 // As 19x20 fp32
#define SMEM_BYTES 108800             // x2 CTAs = 217600

// ===========================================================================
// helpers
// ===========================================================================
__device__ __forceinline__ uint32_t s2u(const void* p) {
    uint32_t a;
    asm("{ .reg .u64 t; cvta.to.shared.u64 t, %1; cvt.u32.u64 %0, t; }"
        : "=r"(a) : "l"(p));
    return a;
}
__device__ __forceinline__ uint32_t h2(float a, float b) {
    __half2 t = __floats2half2_rn(a, b);     // a -> low half
    return *reinterpret_cast<uint32_t*>(&t);
}
__device__ __forceinline__ void sts16(uint32_t addr, uint32_t a, uint32_t b,
                                      uint32_t c, uint32_t d) {
    asm volatile("st.shared.v4.b32 [%0], {%1,%2,%3,%4};"
                 :: "r"(addr), "r"(a), "r"(b), "r"(c), "r"(d) : "memory");
}
__device__ __forceinline__ void sts8f(uint32_t addr, float a, float b) {
    asm volatile("st.shared.v2.f32 [%0], {%1,%2};"
                 :: "r"(addr), "f"(a), "f"(b) : "memory");
}
__device__ __forceinline__ void sts4(uint32_t addr, uint32_t v) {
    asm volatile("st.shared.b32 [%0], %1;" :: "r"(addr), "r"(v) : "memory");
}
__device__ __forceinline__ uint32_t lds4(uint32_t addr) {
    uint32_t v;
    asm volatile("ld.shared.b32 %0, [%1];" : "=r"(v) : "r"(addr));
    return v;
}
__device__ __forceinline__ float2 lds8f(uint32_t addr) {
    float2 v;
    asm volatile("ld.shared.v2.f32 {%0,%1}, [%2];"
                 : "=f"(v.x), "=f"(v.y) : "r"(addr));
    return v;
}
__device__ __forceinline__ float4 lds16f(uint32_t addr) {
    float4 v;
    asm volatile("ld.shared.v4.f32 {%0,%1,%2,%3}, [%4];"
                 : "=f"(v.x), "=f"(v.y), "=f"(v.z), "=f"(v.w) : "r"(addr));
    return v;
}
__device__ __forceinline__ void ldsm4(uint32_t addr, uint32_t& r0, uint32_t& r1,
                                      uint32_t& r2, uint32_t& r3) {
    asm volatile("ldmatrix.sync.aligned.m8n8.x4.shared.b16 {%0,%1,%2,%3}, [%4];"
                 : "=r"(r0), "=r"(r1), "=r"(r2), "=r"(r3) : "r"(addr));
}
__device__ __forceinline__ void mma_f16(float* d, uint32_t a0, uint32_t a1,
                                        uint32_t a2, uint32_t a3,
                                        uint32_t b0, uint32_t b1) {
    asm volatile(
        "mma.sync.aligned.m16n8k16.row.col.f32.f16.f16.f32 "
        "{%0,%1,%2,%3}, {%4,%5,%6,%7}, {%8,%9}, {%0,%1,%2,%3};"
        : "+f"(d[0]), "+f"(d[1]), "+f"(d[2]), "+f"(d[3])
        : "r"(a0), "r"(a1), "r"(a2), "r"(a3), "r"(b0), "r"(b1));
}
__device__ __forceinline__ void cpa16(uint32_t dst, const void* src) {
    asm volatile("cp.async.cg.shared.global [%0], [%1], 16;"
                 :: "r"(dst), "l"(src) : "memory");
}
#define CP_COMMIT() asm volatile("cp.async.commit_group;" ::: "memory")
#define CP_WAIT0()  asm volatile("cp.async.wait_group 0;" ::: "memory")

// 32B rows (16 fp16 = one k16 block), XOR-16B swizzle for conflict-free ldsm
__device__ __forceinline__ uint32_t rowoff(uint32_t r, uint32_t seg) {
    return (r * 32u + seg * 16u) ^ ((r & 4u) << 2);
}
// stage one (row, k16-block): 16 fp32 -> 16 fp16 as 2 x 16B granules
__device__ __forceinline__ void stage16h(uint32_t rowbase, int row,
                                         const float* f) {
    sts16(rowbase + rowoff((uint32_t)row, 0),
          h2(f[0], f[1]), h2(f[2], f[3]), h2(f[4], f[5]), h2(f[6], f[7]));
    sts16(rowbase + rowoff((uint32_t)row, 1),
          h2(f[8], f[9]), h2(f[10], f[11]), h2(f[12], f[13]), h2(f[14], f[15]));
}
// stage X of one tile into buffer at dst (80 rows x 128 k, fp16 swizzled)
__device__ __forceinline__ void stage_x(const float* __restrict__ x, int tile,
                                        uint32_t dst, int tid) {
    for (int u = tid; u < MPAD * 8; u += NTHR) {
        const int row = u >> 3, c = u & 7;
        float f[16];
        if (row < ROWS) {
            const float4* s4 = (const float4*)(x + (size_t)(tile * ROWS + row) * C
                                               + c * 16);
            *(float4*)&f[0]  = s4[0];
            *(float4*)&f[4]  = s4[1];
            *(float4*)&f[8]  = s4[2];
            *(float4*)&f[12] = s4[3];
        } else {
#pragma unroll
            for (int q = 0; q < 16; q++) f[q] = 0.0f;
        }
        stage16h(dst + (uint32_t)c * XBLK, row, f);
    }
}

// ===========================================================================
// Kernel 0 (one-shot, tiny): build swizzled fp16 image of [Wrel;Wroot]
// ===========================================================================
__global__ __launch_bounds__(256) void conv_b(const float* __restrict__ Wrel,
                                              const float* __restrict__ Wroot) {
    const int u = blockIdx.x * 256 + threadIdx.x;   // 2048 units
    const int n = u >> 3, c = u & 7;
    const float* src = (n < 128) ? Wrel  + (size_t)n * C
                                 : Wroot + (size_t)(n - 128) * C;
    const float4* s4 = (const float4*)(src + c * 16);
    float f[16];
    *(float4*)&f[0]  = s4[0];
    *(float4*)&f[4]  = s4[1];
    *(float4*)&f[8]  = s4[2];
    *(float4*)&f[12] = s4[3];
    char* base = g_Bh + (size_t)c * BBLK;
    *(uint4*)(base + rowoff((uint32_t)n, 0)) =
        make_uint4(h2(f[0], f[1]), h2(f[2], f[3]), h2(f[4], f[5]), h2(f[6], f[7]));
    *(uint4*)(base + rowoff((uint32_t)n, 1)) =
        make_uint4(h2(f[8], f[9]), h2(f[10], f[11]), h2(f[12], f[13]),
                   h2(f[14], f[15]));
}

// ===========================================================================
// Fused persistent kernel: 1-2 tiles per CTA, pipelined.
//   MMA1: [P|Q](76x256) = X(76x128) @ [Wrel;Wroot]^T   (fp16 MMA)
//   phase2: out = As(19x19) @ P + Q + b                (fp32 FFMA)
// P fp16 in the just-consumed X buffer; Q fp32 in the B region.
// ===========================================================================
__global__ __launch_bounds__(NTHR, 2) void fused_kernel(
        const float* __restrict__ x,
        const float* __restrict__ ew,
        const float* __restrict__ brel,
        float* __restrict__ out) {
    extern __shared__ __align__(16) char smem[];
    const uint32_t sb = s2u(smem);
    float* As = (float*)(smem + ASOFF);

    const int tid  = threadIdx.x;
    const int wid  = tid >> 5;
    const int lane = tid & 31;
    const int blk  = blockIdx.x;
    const int nt   = (blk < TILES2) ? 2 : 1;
    const int t0   = (blk < TILES2) ? blk * 2 : blk + TILES2;

    // ---- prologue: B cp.async, As build, X(tile0) staging
#pragma unroll
    for (int q = 0; q < 16; q++) {
        const uint32_t off = (uint32_t)(tid * 16 + q * 4096);
        cpa16(sb + BOFF + off, g_Bh + off);
    }
    CP_COMMIT();

    for (int e = tid; e < N_EL * N_EL; e += NTHR) {
        const int j = e / N_EL, i = e % N_EL;
        float w = 0.0f;
        if (i != j) {
            const int r = (j < i) ? j : (j - 1);
            w = ew[i * (N_EL - 1) + r];
        }
        As[j * 20 + i] = w;
    }

    stage_x(x, t0, sb + X0OFF, tid);
    CP_WAIT0();
    __syncthreads();

    // fragment lane addressing (constant)
    const int tt = lane >> 3;
    const int rr = lane & 7;
    const int fr = lane >> 2;
    const int fc = lane & 3;
    const uint32_t a_ld = rowoff((uint32_t)((tt & 1) * 8 + rr), (uint32_t)(tt >> 1));
    const uint32_t b_ld = rowoff((uint32_t)((tt >> 1) * 8 + rr), (uint32_t)(tt & 1));

    for (int t = 0; t < nt; t++) {
        const int tile = t0 + t;
        const uint32_t xb = sb + ((t & 1) ? X1OFF : X0OFF);

        // ---- MMA1: warp = 32-col slab, rows 0..79, K=128
        float acc[5][4][4];
#pragma unroll
        for (int mt = 0; mt < 5; mt++)
#pragma unroll
            for (int n8 = 0; n8 < 4; n8++)
#pragma unroll
                for (int q = 0; q < 4; q++)
                    acc[mt][n8][q] = 0.0f;

#pragma unroll
        for (int c = 0; c < 8; c++) {
            uint32_t nb[4][2];
#pragma unroll
            for (int p = 0; p < 2; p++) {
                uint32_t r0, r1, r2, r3;
                ldsm4(sb + BOFF + (uint32_t)c * BBLK
                      + (uint32_t)(wid * 1024 + p * 512) + b_ld, r0, r1, r2, r3);
                nb[p * 2 + 0][0] = r0; nb[p * 2 + 0][1] = r1;
                nb[p * 2 + 1][0] = r2; nb[p * 2 + 1][1] = r3;
            }
#pragma unroll
            for (int mt = 0; mt < 5; mt++) {
                uint32_t a0, a1, a2, a3;
                ldsm4(xb + (uint32_t)c * XBLK + (uint32_t)(mt * 512) + a_ld,
                      a0, a1, a2, a3);
#pragma unroll
                for (int n8 = 0; n8 < 4; n8++)
                    mma_f16(acc[mt][n8], a0, a1, a2, a3, nb[n8][0], nb[n8][1]);
            }
        }
        __syncthreads();   // MMA1 done: B region -> Q, xb -> P

        // ---- writeback: warps 0-3 -> P fp16 (into xb); warps 4-7 -> Q fp32
        if (wid < 4) {
#pragma unroll
            for (int mt = 0; mt < 5; mt++)
#pragma unroll
                for (int n8 = 0; n8 < 4; n8++) {
                    const int c0 = wid * 32 + n8 * 8 + fc * 2;
#pragma unroll
                    for (int half = 0; half < 2; half++) {
                        const int r = mt * 16 + fr + half * 8;
                        if (r < ROWS)
                            sts4(xb + (uint32_t)(r * PSTR) + (uint32_t)(c0 * 2),
                                 h2(acc[mt][n8][half * 2],
                                    acc[mt][n8][half * 2 + 1]));
                    }
                }
        } else {
#pragma unroll
            for (int mt = 0; mt < 5; mt++)
#pragma unroll
                for (int n8 = 0; n8 < 4; n8++) {
                    const int cq = (wid - 4) * 32 + n8 * 8 + fc * 2;
#pragma unroll
                    for (int half = 0; half < 2; half++) {
                        const int r = mt * 16 + fr + half * 8;
                        if (r < ROWS)
                            sts8f(sb + QOFF + (uint32_t)(r * QSTR)
                                  + (uint32_t)(cq * 4),
                                  acc[mt][n8][half * 2],
                                  acc[mt][n8][half * 2 + 1]);
                    }
                }
        }
        __syncthreads();   // P/Q visible

        // ---- prefetch next tile's X into the other buffer (off critical path)
        if (t + 1 < nt)
            stage_x(x, tile + 1, sb + (((t + 1) & 1) ? X1OFF : X0OFF), tid);

        // ---- phase 2: thread = (graph g, col pair cp)
        {
            const int g  = tid >> 6;                 // 0..3
            const int cp = (tid & 63) * 2;           // even col 0..126
            const float2 bv = *(const float2*)(brel + cp);
            float2 p[N_EL];
#pragma unroll
            for (int i = 0; i < N_EL; i++) {
                const uint32_t u = lds4(xb + (uint32_t)((g * N_EL + i) * PSTR)
                                        + (uint32_t)(cp * 2));
                p[i] = __half22float2(*(const __half2*)&u);
            }
#pragma unroll
            for (int j = 0; j < N_EL; j++) {
                const uint32_t ab = sb + ASOFF + (uint32_t)j * 80u;
                float a[20];
                *(float4*)&a[0]  = lds16f(ab);
                *(float4*)&a[4]  = lds16f(ab + 16u);
                *(float4*)&a[8]  = lds16f(ab + 32u);
                *(float4*)&a[12] = lds16f(ab + 48u);
                *(float4*)&a[16] = lds16f(ab + 64u);
                float2 o = lds8f(sb + QOFF + (uint32_t)((g * N_EL + j) * QSTR)
                                 + (uint32_t)(cp * 4));
                o.x += bv.x; o.y += bv.y;
#pragma unroll
                for (int i = 0; i < N_EL; i++) {
                    o.x = fmaf(a[i], p[i].x, o.x);
                    o.y = fmaf(a[i], p[i].y, o.y);
                }
                *(float2*)(out + (size_t)(tile * ROWS + g * N_EL + j) * C + cp) = o;
            }
        }
        __syncthreads();   // Q/B region free, P/xb free

        // ---- restage B for next tile (Q overwrote part of it)
        if (t + 1 < nt) {
#pragma unroll
            for (int q = 0; q < 16; q++) {
                const uint32_t off = (uint32_t)(tid * 16 + q * 4096);
                cpa16(sb + BOFF + off, g_Bh + off);
            }
            CP_COMMIT();
            CP_WAIT0();
            __syncthreads();
        }
    }
}

// ===========================================================================
// inputs (metadata order): x, edge_index, edge_weights, W_rel, b_rel, W_root
// ===========================================================================
extern "C" void kernel_launch(void* const* d_in, const int* in_sizes, int n_in,
                              void* d_out, int out_size) {
    const float* x     = (const float*)d_in[0];
    const float* ew    = (const float*)d_in[2];
    const float* Wrel  = (const float*)d_in[3];
    const float* brel  = (const float*)d_in[4];
    const float* Wroot = (const float*)d_in[5];
    float* out = (float*)d_out;

    cudaFuncSetAttribute(fused_kernel, cudaFuncAttributeMaxDynamicSharedMemorySize,
                         SMEM_BYTES);

    conv_b<<<8, 256>>>(Wrel, Wroot);
    fused_kernel<<<GRID, NTHR, SMEM_BYTES>>>(x, ew, brel, out);
}

// round 17
// speedup vs baseline: 1.1190x; 1.1190x over previous
#include <cuda_runtime.h>
#include <cuda_fp16.h>
#include <cstdint>

#define N_EL     19
#define GPC      4                    // graphs per CTA
#define ROWS     76                   // valid rows
#define MPAD     80                   // 5 m16 tiles
#define N_GRAPHS 1800
#define C        128
#define GRID     (N_GRAPHS / GPC)     // 450
#define NTHR     256

// pre-converted B image: [Wrel;Wroot] fp16, swizzled smem layout, 64 KB
__device__ __align__(16) char g_Bh[65536];

// smem map (bytes from dynamic base)
#define BOFF   0                      // B fp16: 8 k16-blocks x 256 rows x 32B
#define BBLK   8192
#define QOFF   0                      // Q fp32 overlays B after MMA1: 76 x 528B
#define QSTR   528
#define XOFF   65536                  // X fp16 (staging): 8 blocks x 80r x 32B
#define XBLK   2576                   // padded stride -> conflict-free STS
#define PSTR   272                    // P fp16 row-major, 16B-aligned stride
#define ZROW   (XOFF + 20672)         // 272B zero row (k >= 19 redirect)
#define AHOFF  86480                  // Ah fp16 32x32 (2 k-blocks x 1KB)
#define SMEM_BYTES 88576              // x2 CTAs = 177152

// ===========================================================================
// helpers
// ===========================================================================
__device__ __forceinline__ uint32_t s2u(const void* p) {
    uint32_t a;
    asm("{ .reg .u64 t; cvta.to.shared.u64 t, %1; cvt.u32.u64 %0, t; }"
        : "=r"(a) : "l"(p));
    return a;
}
__device__ __forceinline__ uint32_t h2(float a, float b) {
    __half2 t = __floats2half2_rn(a, b);     // a -> low half
    return *reinterpret_cast<uint32_t*>(&t);
}
__device__ __forceinline__ void sts16(uint32_t addr, uint32_t a, uint32_t b,
                                      uint32_t c, uint32_t d) {
    asm volatile("st.shared.v4.b32 [%0], {%1,%2,%3,%4};"
                 :: "r"(addr), "r"(a), "r"(b), "r"(c), "r"(d) : "memory");
}
__device__ __forceinline__ void sts8f(uint32_t addr, float a, float b) {
    asm volatile("st.shared.v2.f32 [%0], {%1,%2};"
                 :: "r"(addr), "f"(a), "f"(b) : "memory");
}
__device__ __forceinline__ void sts4(uint32_t addr, uint32_t v) {
    asm volatile("st.shared.b32 [%0], %1;" :: "r"(addr), "r"(v) : "memory");
}
__device__ __forceinline__ void sts2h(uint32_t addr, float v) {
    __half h = __float2half_rn(v);
    uint16_t u = *reinterpret_cast<uint16_t*>(&h);
    asm volatile("st.shared.u16 [%0], %1;" :: "r"(addr), "h"(u) : "memory");
}
__device__ __forceinline__ float2 lds8f(uint32_t addr) {
    float2 v;
    asm volatile("ld.shared.v2.f32 {%0,%1}, [%2];"
                 : "=f"(v.x), "=f"(v.y) : "r"(addr));
    return v;
}
__device__ __forceinline__ void ldsm4(uint32_t addr, uint32_t& r0, uint32_t& r1,
                                      uint32_t& r2, uint32_t& r3) {
    asm volatile("ldmatrix.sync.aligned.m8n8.x4.shared.b16 {%0,%1,%2,%3}, [%4];"
                 : "=r"(r0), "=r"(r1), "=r"(r2), "=r"(r3) : "r"(addr));
}
__device__ __forceinline__ void ldsm4t(uint32_t addr, uint32_t& r0, uint32_t& r1,
                                       uint32_t& r2, uint32_t& r3) {
    asm volatile("ldmatrix.sync.aligned.m8n8.x4.trans.shared.b16 {%0,%1,%2,%3}, [%4];"
                 : "=r"(r0), "=r"(r1), "=r"(r2), "=r"(r3) : "r"(addr));
}
__device__ __forceinline__ void mma_f16(float* d, uint32_t a0, uint32_t a1,
                                        uint32_t a2, uint32_t a3,
                                        uint32_t b0, uint32_t b1) {
    asm volatile(
        "mma.sync.aligned.m16n8k16.row.col.f32.f16.f16.f32 "
        "{%0,%1,%2,%3}, {%4,%5,%6,%7}, {%8,%9}, {%0,%1,%2,%3};"
        : "+f"(d[0]), "+f"(d[1]), "+f"(d[2]), "+f"(d[3])
        : "r"(a0), "r"(a1), "r"(a2), "r"(a3), "r"(b0), "r"(b1));
}
__device__ __forceinline__ void cpa16(uint32_t dst, const void* src) {
    asm volatile("cp.async.cg.shared.global [%0], [%1], 16;"
                 :: "r"(dst), "l"(src) : "memory");
}
#define CP_COMMIT() asm volatile("cp.async.commit_group;" ::: "memory")
#define CP_WAIT0()  asm volatile("cp.async.wait_group 0;" ::: "memory")

// 32B rows (16 fp16 = one k16 block), XOR-16B swizzle for conflict-free ldsm
__device__ __forceinline__ uint32_t rowoff(uint32_t r, uint32_t seg) {
    return (r * 32u + seg * 16u) ^ ((r & 4u) << 2);
}
// stage one (row, k16-block): 16 fp32 -> 16 fp16 as 2 x 16B granules
__device__ __forceinline__ void stage16h(uint32_t rowbase, int row,
                                         const float* f) {
    sts16(rowbase + rowoff((uint32_t)row, 0),
          h2(f[0], f[1]), h2(f[2], f[3]), h2(f[4], f[5]), h2(f[6], f[7]));
    sts16(rowbase + rowoff((uint32_t)row, 1),
          h2(f[8], f[9]), h2(f[10], f[11]), h2(f[12], f[13]), h2(f[14], f[15]));
}

// ===========================================================================
// Kernel 0 (one-shot, tiny): build swizzled fp16 image of [Wrel;Wroot]
// ===========================================================================
__global__ __launch_bounds__(256) void conv_b(const float* __restrict__ Wrel,
                                              const float* __restrict__ Wroot) {
    const int u = blockIdx.x * 256 + threadIdx.x;   // 2048 units
    const int n = u >> 3, c = u & 7;
    const float* src = (n < 128) ? Wrel  + (size_t)n * C
                                 : Wroot + (size_t)(n - 128) * C;
    const float4* s4 = (const float4*)(src + c * 16);
    float f[16];
    *(float4*)&f[0]  = s4[0];
    *(float4*)&f[4]  = s4[1];
    *(float4*)&f[8]  = s4[2];
    *(float4*)&f[12] = s4[3];
    char* base = g_Bh + (size_t)c * BBLK;
    *(uint4*)(base + rowoff((uint32_t)n, 0)) =
        make_uint4(h2(f[0], f[1]), h2(f[2], f[3]), h2(f[4], f[5]), h2(f[6], f[7]));
    *(uint4*)(base + rowoff((uint32_t)n, 1)) =
        make_uint4(h2(f[8], f[9]), h2(f[10], f[11]), h2(f[12], f[13]),
                   h2(f[14], f[15]));
}

// ===========================================================================
// Fused kernel:
//   MMA1: [P|Q](76x256) = X(76x128) @ [Wrel;Wroot]^T   (fp16 MMA)
//   MMA2: out_g = Ah(19x19) @ P_g + (Q_g + b)          (fp16 MMA, trans-B)
// P fp16 row-major in the dead X buffer; B operand of MMA2 loaded with
// ldmatrix.trans (no scatter writeback); k>=19 rows redirect to a zero row.
// ===========================================================================
__global__ __launch_bounds__(NTHR, 2) void fused_kernel(
        const float* __restrict__ x,
        const float* __restrict__ ew,
        const float* __restrict__ brel,
        float* __restrict__ out) {
    extern __shared__ __align__(16) char smem[];
    const uint32_t sb = s2u(smem);

    const int tid  = threadIdx.x;
    const int wid  = tid >> 5;
    const int lane = tid & 31;
    const int blk  = blockIdx.x;

    // ---- B staging: linear 64KB cp.async memcpy (issued first)
#pragma unroll
    for (int q = 0; q < 16; q++) {
        const uint32_t off = (uint32_t)(tid * 16 + q * 4096);
        cpa16(sb + BOFF + off, g_Bh + off);
    }
    CP_COMMIT();

    // ---- zero row for MMA2 k-padding
    if (tid < 17)
        sts16(sb + ZROW + (uint32_t)(tid * 16), 0u, 0u, 0u, 0u);

    // ---- build Ah: 32x32 fp16 (zero-padded), swizzled for ldmatrix
    for (int e = tid; e < 32 * 32; e += NTHR) {
        const int j = e >> 5, i = e & 31;
        float w = 0.0f;
        if (i < N_EL && j < N_EL && i != j) {
            const int r = (j < i) ? j : (j - 1);
            w = ew[i * (N_EL - 1) + r];
        }
        sts2h(sb + AHOFF + (uint32_t)((i >> 4) * 1024) + rowoff((uint32_t)j,
              (uint32_t)((i & 15) >> 3)) + (uint32_t)((i & 7) * 2), w);
    }

    // ---- stage X: 640 units (row 0..79, k16-block 0..7)
    for (int u = tid; u < MPAD * 8; u += NTHR) {
        const int row = u >> 3, c = u & 7;
        float f[16];
        if (row < ROWS) {
            const float4* s4 = (const float4*)(x + (size_t)(blk * ROWS + row) * C
                                               + c * 16);
            *(float4*)&f[0]  = s4[0];
            *(float4*)&f[4]  = s4[1];
            *(float4*)&f[8]  = s4[2];
            *(float4*)&f[12] = s4[3];
        } else {
#pragma unroll
            for (int q = 0; q < 16; q++) f[q] = 0.0f;
        }
        stage16h(sb + XOFF + (uint32_t)c * XBLK, row, f);
    }
    CP_WAIT0();
    __syncthreads();

    // fragment lane addressing
    const int tt = lane >> 3;
    const int rr = lane & 7;
    const int fr = lane >> 2;
    const int fc = lane & 3;
    const uint32_t a_ld = rowoff((uint32_t)((tt & 1) * 8 + rr), (uint32_t)(tt >> 1));
    const uint32_t b_ld = rowoff((uint32_t)((tt >> 1) * 8 + rr), (uint32_t)(tt & 1));

    // ---- MMA1: warp covers n-cols [wid*32, +32), rows 0..79, K=128
    float acc[5][4][4];
#pragma unroll
    for (int mt = 0; mt < 5; mt++)
#pragma unroll
        for (int n8 = 0; n8 < 4; n8++)
#pragma unroll
            for (int q = 0; q < 4; q++)
                acc[mt][n8][q] = 0.0f;

#pragma unroll
    for (int c = 0; c < 8; c++) {
        uint32_t nb[4][2];
#pragma unroll
        for (int p = 0; p < 2; p++) {
            uint32_t r0, r1, r2, r3;
            ldsm4(sb + BOFF + (uint32_t)c * BBLK + (uint32_t)(wid * 1024 + p * 512)
                  + b_ld, r0, r1, r2, r3);
            nb[p * 2 + 0][0] = r0; nb[p * 2 + 0][1] = r1;
            nb[p * 2 + 1][0] = r2; nb[p * 2 + 1][1] = r3;
        }
#pragma unroll
        for (int mt = 0; mt < 5; mt++) {
            uint32_t a0, a1, a2, a3;
            ldsm4(sb + XOFF + (uint32_t)c * XBLK + (uint32_t)(mt * 512) + a_ld,
                  a0, a1, a2, a3);
#pragma unroll
            for (int n8 = 0; n8 < 4; n8++)
                mma_f16(acc[mt][n8], a0, a1, a2, a3, nb[n8][0], nb[n8][1]);
        }
    }
    __syncthreads();   // X/B reads done -> X region -> P, B region -> Q

    // ---- writeback: warps 0-3 -> P fp16 row-major; warps 4-7 -> Q fp32
    if (wid < 4) {
#pragma unroll
        for (int mt = 0; mt < 5; mt++)
#pragma unroll
            for (int n8 = 0; n8 < 4; n8++) {
                const int c0 = wid * 32 + n8 * 8 + fc * 2;
#pragma unroll
                for (int half = 0; half < 2; half++) {
                    const int r = mt * 16 + fr + half * 8;
                    if (r < ROWS)
                        sts4(sb + XOFF + (uint32_t)(r * PSTR) + (uint32_t)(c0 * 2),
                             h2(acc[mt][n8][half * 2], acc[mt][n8][half * 2 + 1]));
                }
            }
    } else {
#pragma unroll
        for (int mt = 0; mt < 5; mt++)
#pragma unroll
            for (int n8 = 0; n8 < 4; n8++) {
                const int cq = (wid - 4) * 32 + n8 * 8 + fc * 2;
#pragma unroll
                for (int half = 0; half < 2; half++) {
                    const int r = mt * 16 + fr + half * 8;
                    if (r < ROWS)
                        sts8f(sb + QOFF + (uint32_t)(r * QSTR) + (uint32_t)(cq * 4),
                              acc[mt][n8][half * 2], acc[mt][n8][half * 2 + 1]);
                }
            }
    }
    __syncthreads();

    // ---- MMA2: warp = (graph g, 64-col half nh); out = Ah@P + (Q + b)
    {
        const int g  = wid >> 1;
        const int nh = wid & 1;

        // A fragments (j-pad 32 rows, k-pad 32)
        uint32_t af[2][2][4];
#pragma unroll
        for (int mt2 = 0; mt2 < 2; mt2++)
#pragma unroll
            for (int kb = 0; kb < 2; kb++)
                ldsm4(sb + AHOFF + (uint32_t)(kb * 1024 + mt2 * 512) + a_ld,
                      af[mt2][kb][0], af[mt2][kb][1], af[mt2][kb][2],
                      af[mt2][kb][3]);

        // init accumulators from Q + bias
        float d2[2][8][4];
#pragma unroll
        for (int n8 = 0; n8 < 8; n8++) {
            const int cg = nh * 64 + n8 * 8 + fc * 2;
            const float2 bv = *(const float2*)(brel + cg);
#pragma unroll
            for (int mt2 = 0; mt2 < 2; mt2++)
#pragma unroll
                for (int half = 0; half < 2; half++) {
                    const int j = mt2 * 16 + fr + half * 8;
                    if (j < N_EL) {
                        float2 q = lds8f(sb + QOFF
                                         + (uint32_t)((g * N_EL + j) * QSTR)
                                         + (uint32_t)(cg * 4));
                        d2[mt2][n8][half * 2]     = q.x + bv.x;
                        d2[mt2][n8][half * 2 + 1] = q.y + bv.y;
                    } else {
                        d2[mt2][n8][half * 2] = 0.0f;
                        d2[mt2][n8][half * 2 + 1] = 0.0f;
                    }
                }
        }

        // k loop: B fragments from row-major P via ldmatrix.trans
        const int k_lane  = (tt & 1) * 8 + rr;
        const int ncol_b  = (nh * 64 + (tt >> 1) * 8) * 2;
#pragma unroll
        for (int kb = 0; kb < 2; kb++) {
            const int k = kb * 16 + k_lane;
            const uint32_t rowb = (k < N_EL)
                ? sb + XOFF + (uint32_t)((g * N_EL + k) * PSTR + ncol_b)
                : sb + ZROW + (uint32_t)((tt >> 1) * 16);
            uint32_t pb[8][2];
#pragma unroll
            for (int np = 0; np < 4; np++) {
                uint32_t r0, r1, r2, r3;
                ldsm4t(rowb + (uint32_t)(np * 32), r0, r1, r2, r3);
                pb[np * 2 + 0][0] = r0; pb[np * 2 + 0][1] = r1;
                pb[np * 2 + 1][0] = r2; pb[np * 2 + 1][1] = r3;
            }
#pragma unroll
            for (int mt2 = 0; mt2 < 2; mt2++)
#pragma unroll
                for (int n8 = 0; n8 < 8; n8++)
                    mma_f16(d2[mt2][n8], af[mt2][kb][0], af[mt2][kb][1],
                            af[mt2][kb][2], af[mt2][kb][3],
                            pb[n8][0], pb[n8][1]);
        }

        // store valid rows
#pragma unroll
        for (int mt2 = 0; mt2 < 2; mt2++)
#pragma unroll
            for (int n8 = 0; n8 < 8; n8++) {
                const int cg = nh * 64 + n8 * 8 + fc * 2;
#pragma unroll
                for (int half = 0; half < 2; half++) {
                    const int j = mt2 * 16 + fr + half * 8;
                    if (j < N_EL) {
                        float2 o = make_float2(d2[mt2][n8][half * 2],
                                               d2[mt2][n8][half * 2 + 1]);
                        *(float2*)(out + (size_t)(blk * ROWS + g * N_EL + j) * C
                                   + cg) = o;
                    }
                }
            }
    }
}

// ===========================================================================
// inputs (metadata order): x, edge_index, edge_weights, W_rel, b_rel, W_root
// ===========================================================================
extern "C" void kernel_launch(void* const* d_in, const int* in_sizes, int n_in,
                              void* d_out, int out_size) {
    const float* x     = (const float*)d_in[0];
    const float* ew    = (const float*)d_in[2];
    const float* Wrel  = (const float*)d_in[3];
    const float* brel  = (const float*)d_in[4];
    const float* Wroot = (const float*)d_in[5];
    float* out = (float*)d_out;

    cudaFuncSetAttribute(fused_kernel, cudaFuncAttributeMaxDynamicSharedMemorySize,
                         SMEM_BYTES);

    conv_b<<<8, 256>>>(Wrel, Wroot);
    fused_kernel<<<GRID, NTHR, SMEM_BYTES>>>(x, ew, brel, out);
}